// round 14
// baseline (speedup 1.0000x reference)
#include <cuda_runtime.h>
#include <math.h>
#include <stdint.h>

#define Nn   32
#define Cc   64
#define Tt   64
#define Vv   204
#define Hh   3
#define QKd  16
#define Pp   13056
#define OQKV 96
#define HC   192
#define NB   16

__device__ float d_h   [(size_t)Nn * Cc * Pp + 64];
__device__ float d_g   [(size_t)Nn * Cc * Pp + 64];
__device__ float d_qk  [(size_t)Nn * OQKV * Pp + 64];
__device__ float d_wpe [(size_t)OQKV * Pp];
__device__ float d_att [(size_t)Nn * Hh * Tt * Tt];
__device__ float d_attp[(size_t)4 * Nn * Hh * Tt * Tt];
__device__ float d_G2  [(size_t)Nn * HC * Pp + 64];
__device__ float d_wt  [4096 + 6144 + 4096 + 12288];
__device__ float d_A2  [208 * 208];

#define WT_GCN 0
#define WT_QKV 4096
#define WT_FF  10240
#define WT_W2  14336

enum { MODE_BIAS = 0, MODE_ADD2D = 1, MODE_BN_RES_LEAKY = 2, MODE_NONE = 3 };

__device__ __forceinline__ unsigned cvt_tf32(float f) {
    unsigned u; asm("cvt.rna.tf32.f32 %0, %1;" : "=r"(u) : "f"(f)); return u;
}
__device__ __forceinline__ float rna_f(float f) { return __uint_as_float(cvt_tf32(f)); }

__device__ __forceinline__ void mma8(float* d, const unsigned* a, const unsigned* b) {
    asm volatile(
        "mma.sync.aligned.m16n8k8.row.col.f32.tf32.tf32.f32 "
        "{%0,%1,%2,%3},{%4,%5,%6,%7},{%8,%9},{%0,%1,%2,%3};"
        : "+f"(d[0]), "+f"(d[1]), "+f"(d[2]), "+f"(d[3])
        : "r"(a[0]), "r"(a[1]), "r"(a[2]), "r"(a[3]), "r"(b[0]), "r"(b[1]));
}
__device__ __forceinline__ uint32_t smem_u32(const void* p) {
    return (uint32_t)__cvta_generic_to_shared(p);
}
__device__ __forceinline__ void cpa16(uint32_t dst, const void* src) {
    asm volatile("cp.async.cg.shared.global [%0],[%1],16;" :: "r"(dst), "l"(src));
}
__device__ __forceinline__ void cpa16z(uint32_t dst, const void* src, int sz) {
    asm volatile("cp.async.cg.shared.global [%0],[%1],16,%2;" :: "r"(dst), "l"(src), "r"(sz));
}
#define CP_COMMIT() asm volatile("cp.async.commit_group;")
#define CP_WAIT2()  asm volatile("cp.async.wait_group 2;")

// ============================================================================
__global__ void prep_kernel(const float* __restrict__ gcn_w, const float* __restrict__ qkv_w,
                            const float* __restrict__ ff_w, const float* __restrict__ on_w,
                            const float* __restrict__ A,
                            float* __restrict__ wt, float* __restrict__ A2)
{
    int i = blockIdx.x * 256 + threadIdx.x;
    if (i < 4096) { wt[WT_GCN + i] = rna_f(gcn_w[i]); return; }
    i -= 4096;
    if (i < 6144) { wt[WT_QKV + i] = rna_f(qkv_w[i]); return; }
    i -= 6144;
    if (i < 4096) { wt[WT_FF + i] = rna_f(ff_w[i]); return; }
    i -= 4096;
    if (i < 12288) {
        int o = i >> 6, cc = i & 63;
        int s = o >> 6, c = o & 63;
        wt[WT_W2 + i] = rna_f(on_w[(size_t)c * HC + s * 64 + cc]);
        return;
    }
    i -= 12288;
    if (i < 208 * 208) {
        int u = i / 208, v = i % 208;
        A2[i] = (u < 204 && v < 204) ? rna_f(A[(size_t)u * 204 + v]) : 0.f;
    }
}

// ============================================================================
// conv_mma (R5 + batch offset)
// ============================================================================
#define CV_ASZ (64 * 20)
#define CV_BSZ (16 * 264)
#define CV_SMEM (4 * (CV_ASZ + CV_BSZ) * 4)

template <int MODE, int ROUND>
__global__ __launch_bounds__(256, 2)
void conv_mma(const float* __restrict__ in, const float* __restrict__ Wt,
              const float* __restrict__ bias, const float* __restrict__ add2d,
              const float* __restrict__ res,
              const float* __restrict__ bng, const float* __restrict__ bnb,
              const float* __restrict__ bnm, const float* __restrict__ bnv,
              float* __restrict__ out, int Kc, int Oc, int nbase)
{
    extern __shared__ float sm[];
    float* As = sm;
    float* Bs = sm + 4 * CV_ASZ;

    const int n  = blockIdx.z + nbase;
    const int pt = blockIdx.x * 256;
    const int ot = blockIdx.y * 64;
    const int tid = threadIdx.x, lane = tid & 31, warp = tid >> 5;
    const int wm = warp & 1, wn = warp >> 1;
    const int m0 = wm * 32, n0 = wn * 64;
    const int lr = lane >> 2, kc = lane & 3;

    const float* inN = in + (size_t)n * Kc * Pp + pt;
    const int NCH = Kc >> 4;

    float acc[2][8][4];
    #pragma unroll
    for (int f = 0; f < 2; f++)
        #pragma unroll
        for (int j = 0; j < 8; j++)
            #pragma unroll
            for (int q = 0; q < 4; q++) acc[f][j][q] = 0.f;

    auto prefetch = [&](int c, int stage) {
        float* BsS = Bs + stage * CV_BSZ;
        const float* bsrc = inN + (size_t)(c * 16) * Pp;
        #pragma unroll
        for (int i = 0; i < 4; i++) {
            int e = tid + 256 * i;
            int k = e >> 6, grp = e & 63;
            cpa16(smem_u32(&BsS[k * 264 + grp * 4]), bsrc + (size_t)k * Pp + grp * 4);
        }
        float* AsS = As + stage * CV_ASZ;
        int arow = tid >> 2, agrp = tid & 3;
        int o = ot + arow;
        int ok = (o < Oc);
        cpa16z(smem_u32(&AsS[arow * 20 + agrp * 4]),
               ok ? (Wt + (size_t)o * Kc + c * 16 + agrp * 4) : Wt, ok ? 16 : 0);
    };

    prefetch(0, 0); CP_COMMIT();
    if (NCH > 1) prefetch(1, 1);
    CP_COMMIT();

    for (int c = 0; c < NCH; c++) {
        if (c + 2 < NCH) prefetch(c + 2, (c + 2) & 3);
        CP_COMMIT();
        CP_WAIT2();
        __syncthreads();

        const float* AsS = As + (c & 3) * CV_ASZ;
        const float* BsS = Bs + (c & 3) * CV_BSZ;
        #pragma unroll
        for (int g = 0; g < 2; g++) {
            unsigned a[2][4];
            #pragma unroll
            for (int f = 0; f < 2; f++) {
                a[f][0] = __float_as_uint(AsS[(m0 + f * 16 + lr    ) * 20 + g * 8 + kc    ]);
                a[f][1] = __float_as_uint(AsS[(m0 + f * 16 + lr + 8) * 20 + g * 8 + kc    ]);
                a[f][2] = __float_as_uint(AsS[(m0 + f * 16 + lr    ) * 20 + g * 8 + kc + 4]);
                a[f][3] = __float_as_uint(AsS[(m0 + f * 16 + lr + 8) * 20 + g * 8 + kc + 4]);
            }
            #pragma unroll
            for (int j = 0; j < 8; j++) {
                unsigned b[2];
                b[0] = __float_as_uint(BsS[(g * 8 + kc    ) * 264 + n0 + 8 * j + lr]);
                b[1] = __float_as_uint(BsS[(g * 8 + kc + 4) * 264 + n0 + 8 * j + lr]);
                mma8(acc[0][j], a[0], b);
                mma8(acc[1][j], a[1], b);
            }
        }
    }

    #pragma unroll
    for (int f = 0; f < 2; f++) {
        #pragma unroll
        for (int half = 0; half < 2; half++) {
            int o = ot + m0 + f * 16 + lr + half * 8;
            if (o >= Oc) continue;
            size_t obase = ((size_t)n * Oc + o) * Pp;
            if (MODE == MODE_NONE) {
                #pragma unroll
                for (int j = 0; j < 8; j++) {
                    int p = pt + n0 + 8 * j + 2 * kc;
                    float va = acc[f][j][half * 2], vb = acc[f][j][half * 2 + 1];
                    if (ROUND) { va = rna_f(va); vb = rna_f(vb); }
                    *(float2*)(out + obase + p) = make_float2(va, vb);
                }
            } else if (MODE == MODE_BIAS) {
                float b = bias[o];
                #pragma unroll
                for (int j = 0; j < 8; j++) {
                    int p = pt + n0 + 8 * j + 2 * kc;
                    float va = acc[f][j][half * 2] + b, vb = acc[f][j][half * 2 + 1] + b;
                    if (ROUND) { va = rna_f(va); vb = rna_f(vb); }
                    *(float2*)(out + obase + p) = make_float2(va, vb);
                }
            } else if (MODE == MODE_ADD2D) {
                size_t abase = (size_t)o * Pp;
                #pragma unroll
                for (int j = 0; j < 8; j++) {
                    int p = pt + n0 + 8 * j + 2 * kc;
                    float2 av = *(const float2*)(add2d + abase + p);
                    float va = acc[f][j][half * 2] + av.x, vb = acc[f][j][half * 2 + 1] + av.y;
                    if (ROUND) { va = rna_f(va); vb = rna_f(vb); }
                    *(float2*)(out + obase + p) = make_float2(va, vb);
                }
            } else {
                float s  = bng[o] * rsqrtf(bnv[o] + 1e-5f);
                float sh = bnb[o] - bnm[o] * s + bias[o] * s;
                #pragma unroll
                for (int j = 0; j < 8; j++) {
                    int p = pt + n0 + 8 * j + 2 * kc;
                    float2 rv = *(const float2*)(res + obase + p);
                    float va = acc[f][j][half * 2]     * s + sh + rv.x;
                    float vb = acc[f][j][half * 2 + 1] * s + sh + rv.y;
                    va = (va > 0.f) ? va : 0.1f * va;
                    vb = (vb > 0.f) ? vb : 0.1f * vb;
                    if (ROUND) { va = rna_f(va); vb = rna_f(vb); }
                    *(float2*)(out + obase + p) = make_float2(va, vb);
                }
            }
        }
    }
}

// ============================================================================
// adj_mma (R10 M=64 version — measured fastest)
// ============================================================================
#define AD_ASZ (64 * 20)
#define AD_BSZ (208 * 20)
#define AD_SMEM (4 * (AD_ASZ + AD_BSZ) * 4)

__global__ __launch_bounds__(256, 2)
void adj_mma(const float* __restrict__ h, const float* __restrict__ A2,
             const float* __restrict__ x,
             const float* __restrict__ bng, const float* __restrict__ bnb,
             const float* __restrict__ bnm, const float* __restrict__ bnv,
             float* __restrict__ out, int rbase)
{
    extern __shared__ float sm[];
    float* As = sm;
    float* Bs = sm + 4 * AD_ASZ;

    const int rt = blockIdx.x * 64 + rbase;
    const int tid = threadIdx.x, lane = tid & 31, warp = tid >> 5;
    const int wm = warp & 3, wn = warp >> 2;
    const int m0 = wm * 16, nb0 = wn * 104;
    const int lr = lane >> 2, kc = lane & 3;

    const int ch  = (rt >> 6) & 63;
    const float s  = bng[ch] * rsqrtf(bnv[ch] + 1e-5f);
    const float sh = bnb[ch] - bnm[ch] * s;

    float acc[13][4];
    #pragma unroll
    for (int j = 0; j < 13; j++)
        #pragma unroll
        for (int q = 0; q < 4; q++) acc[j][q] = 0.f;

    const int arow = tid >> 2, agrp = tid & 3;
    const int NCH = 13;

    auto prefetch = [&](int c, int stage) {
        float* BsS = Bs + stage * AD_BSZ;
        #pragma unroll
        for (int i = 0; i < 4; i++) {
            int e = tid + 256 * i;
            if (e < 832) {
                int u = e >> 2, grp = e & 3;
                cpa16(smem_u32(&BsS[u * 20 + grp * 4]), A2 + (size_t)u * 208 + c * 16 + grp * 4);
            }
        }
        float* AsS = As + stage * AD_ASZ;
        cpa16(smem_u32(&AsS[arow * 20 + agrp * 4]),
              h + (size_t)(rt + arow) * 204 + c * 16 + agrp * 4);
    };

    prefetch(0, 0); CP_COMMIT();
    prefetch(1, 1); CP_COMMIT();

    for (int c = 0; c < NCH; c++) {
        if (c + 2 < NCH) prefetch(c + 2, (c + 2) & 3);
        CP_COMMIT();
        CP_WAIT2();
        __syncthreads();

        const float* AsS = As + (c & 3) * AD_ASZ;
        const float* BsS = Bs + (c & 3) * AD_BSZ;
        #pragma unroll
        for (int g = 0; g < 2; g++) {
            unsigned a[4];
            a[0] = __float_as_uint(AsS[(m0 + lr    ) * 20 + g * 8 + kc    ]);
            a[1] = __float_as_uint(AsS[(m0 + lr + 8) * 20 + g * 8 + kc    ]);
            a[2] = __float_as_uint(AsS[(m0 + lr    ) * 20 + g * 8 + kc + 4]);
            a[3] = __float_as_uint(AsS[(m0 + lr + 8) * 20 + g * 8 + kc + 4]);
            #pragma unroll
            for (int j = 0; j < 13; j++) {
                unsigned b[2];
                b[0] = __float_as_uint(BsS[(nb0 + 8 * j + lr) * 20 + g * 8 + kc    ]);
                b[1] = __float_as_uint(BsS[(nb0 + 8 * j + lr) * 20 + g * 8 + kc + 4]);
                mma8(acc[j], a, b);
            }
        }
    }

    #pragma unroll
    for (int half = 0; half < 2; half++) {
        int r = rt + m0 + lr + half * 8;
        size_t rb = (size_t)r * 204;
        #pragma unroll
        for (int j = 0; j < 13; j++) {
            int u = nb0 + 8 * j + 2 * kc;
            if (u < 204) {
                float2 xv = *(const float2*)(x + rb + u);
                float va = acc[j][half * 2]     * s + sh + xv.x;
                float vb = acc[j][half * 2 + 1] * s + sh + xv.y;
                *(float2*)(out + rb + u) =
                    make_float2(rna_f(fmaxf(va, 0.f)), rna_f(fmaxf(vb, 0.f)));
            }
        }
    }
}

// ============================================================================
// attn_mma / combine / z_mma (R10 verbatim)
// ============================================================================
#define AT_QSZ (64 * 20)
#define AT_SMEM (4 * 2 * AT_QSZ * 4)

__global__ __launch_bounds__(256, 4)
void attn_mma(const float* __restrict__ qk, float* __restrict__ part, int nbase)
{
    extern __shared__ float sm[];
    float* Qs = sm;
    float* Ks = sm + 4 * AT_QSZ;

    const int hh = blockIdx.x, n = blockIdx.y + nbase, z = blockIdx.z;
    const int cc0 = z * 4;
    const int tid = threadIdx.x, lane = tid & 31, warp = tid >> 5;
    const int wm = warp & 3, wn = warp >> 2;
    const int m0 = wm * 16, nb0 = wn * 32;
    const int lr = lane >> 2, kc = lane & 3;

    const float* qbase = qk + ((size_t)n * OQKV + hh * QKd) * Pp;
    const float* kbase = qk + ((size_t)n * OQKV + Hh * QKd + hh * QKd) * Pp;

    const int arow = tid >> 2, agrp = tid & 3;
    const int NCH = 52;

    float acc[4][4];
    #pragma unroll
    for (int j = 0; j < 4; j++)
        #pragma unroll
        for (int q = 0; q < 4; q++) acc[j][q] = 0.f;

    auto prefetch = [&](int c, int stage) {
        int ci = cc0 + (c / 13);
        int vb = (c % 13) * 16;
        int v = vb + agrp * 4;
        int ok = (v < 204);
        const float* qs = qbase + (size_t)ci * Pp + (size_t)arow * 204 + v;
        const float* ks = kbase + (size_t)ci * Pp + (size_t)arow * 204 + v;
        cpa16z(smem_u32(&Qs[stage * AT_QSZ + arow * 20 + agrp * 4]), ok ? qs : qk, ok ? 16 : 0);
        cpa16z(smem_u32(&Ks[stage * AT_QSZ + arow * 20 + agrp * 4]), ok ? ks : qk, ok ? 16 : 0);
    };

    prefetch(0, 0); CP_COMMIT();
    prefetch(1, 1); CP_COMMIT();

    for (int c = 0; c < NCH; c++) {
        if (c + 2 < NCH) prefetch(c + 2, (c + 2) & 3);
        CP_COMMIT();
        CP_WAIT2();
        __syncthreads();

        const float* QsS = Qs + (c & 3) * AT_QSZ;
        const float* KsS = Ks + (c & 3) * AT_QSZ;
        #pragma unroll
        for (int g = 0; g < 2; g++) {
            unsigned a[4];
            a[0] = __float_as_uint(QsS[(m0 + lr    ) * 20 + g * 8 + kc    ]);
            a[1] = __float_as_uint(QsS[(m0 + lr + 8) * 20 + g * 8 + kc    ]);
            a[2] = __float_as_uint(QsS[(m0 + lr    ) * 20 + g * 8 + kc + 4]);
            a[3] = __float_as_uint(QsS[(m0 + lr + 8) * 20 + g * 8 + kc + 4]);
            #pragma unroll
            for (int j = 0; j < 4; j++) {
                unsigned b[2];
                b[0] = __float_as_uint(KsS[(nb0 + 8 * j + lr) * 20 + g * 8 + kc    ]);
                b[1] = __float_as_uint(KsS[(nb0 + 8 * j + lr) * 20 + g * 8 + kc + 4]);
                mma8(acc[j], a, b);
            }
        }
    }

    float* pb = part + (((size_t)z * Nn + n) * Hh + hh) * 4096;
    #pragma unroll
    for (int half = 0; half < 2; half++) {
        int t = m0 + lr + half * 8;
        #pragma unroll
        for (int j = 0; j < 4; j++) {
            int q = nb0 + 8 * j + 2 * kc;
            *(float2*)(pb + (size_t)t * 64 + q) =
                make_float2(acc[j][half * 2], acc[j][half * 2 + 1]);
        }
    }
}

__global__ void attn_combine_kernel(const float* __restrict__ part,
                                    const float* __restrict__ alphas,
                                    const float* __restrict__ att1s,
                                    float* __restrict__ att, int nbase)
{
    int idx = blockIdx.x * blockDim.x + threadIdx.x;
    const int seg_total = NB * Hh * Tt * Tt;
    if (idx >= seg_total) return;
    int tq = idx & (Tt * Tt - 1);
    int rest = idx >> 12;
    int h = rest % Hh;
    int n = nbase + rest / Hh;
    const int total = Nn * Hh * Tt * Tt;
    size_t gi = (((size_t)n * Hh + h) << 12) + tq;
    float p = part[gi] + part[(size_t)total + gi]
            + part[2 * (size_t)total + gi] + part[3 * (size_t)total + gi];
    const float inv = 1.0f / (float)(QKd * Vv);
    att[gi] = rna_f(tanhf(p * inv) * alphas[h] + att1s[(size_t)h * Tt * Tt + tq]);
}

#define ZM_ASZ (16 * 72)
#define ZM_BSZ (16 * 232)
#define ZM_SMEM (4 * (ZM_ASZ + ZM_BSZ) * 4)

__global__ __launch_bounds__(256, 2)
void z_mma(const float* __restrict__ G2, const float* __restrict__ att,
           const float* __restrict__ g,
           const float* __restrict__ on_b, const float* __restrict__ on_g,
           const float* __restrict__ on_bb, const float* __restrict__ on_m,
           const float* __restrict__ on_v,
           float* __restrict__ out, int nbase)
{
    extern __shared__ float sm[];
    float* As = sm;
    float* Bs = sm + 4 * ZM_ASZ;

    const int cch = blockIdx.x, n = blockIdx.y + nbase;
    const int tid = threadIdx.x, lane = tid & 31, warp = tid >> 5;
    const int wm = warp & 3, wn = warp >> 2;
    const int m0 = wm * 16, nb0 = wn * 104;
    const int lr = lane >> 2, kc = lane & 3;

    float acc[13][4];
    #pragma unroll
    for (int j = 0; j < 13; j++)
        #pragma unroll
        for (int q = 0; q < 4; q++) acc[j][q] = 0.f;

    const int NCH = 12;

    auto prefetch = [&](int c, int stage) {
        int s  = c >> 2;
        int tb = (c & 3) * 16;
        const float* gb = G2 + ((size_t)n * HC + s * 64 + cch) * Pp;
        float* BsS = Bs + stage * ZM_BSZ;
        #pragma unroll
        for (int i = 0; i < 4; i++) {
            int e = tid + 256 * i;
            if (e < 832) {
                int trow = e / 52, grp = e % 52;
                int ok = (grp < 51);
                cpa16z(smem_u32(&BsS[trow * 232 + grp * 4]),
                       ok ? (gb + (size_t)(tb + trow) * 204 + grp * 4) : gb, ok ? 16 : 0);
            }
        }
        float* AsS = As + stage * ZM_ASZ;
        int trow = tid >> 4, grp = tid & 15;
        cpa16(smem_u32(&AsS[trow * 72 + grp * 4]),
              att + ((size_t)(n * Hh + s)) * 4096 + (size_t)(tb + trow) * 64 + grp * 4);
    };

    prefetch(0, 0); CP_COMMIT();
    prefetch(1, 1); CP_COMMIT();

    for (int c = 0; c < NCH; c++) {
        if (c + 2 < NCH) prefetch(c + 2, (c + 2) & 3);
        CP_COMMIT();
        CP_WAIT2();
        __syncthreads();

        const float* AsS = As + (c & 3) * ZM_ASZ;
        const float* BsS = Bs + (c & 3) * ZM_BSZ;
        #pragma unroll
        for (int g8 = 0; g8 < 2; g8++) {
            unsigned a[4];
            a[0] = __float_as_uint(AsS[(g8 * 8 + kc    ) * 72 + m0 + lr    ]);
            a[1] = __float_as_uint(AsS[(g8 * 8 + kc    ) * 72 + m0 + lr + 8]);
            a[2] = __float_as_uint(AsS[(g8 * 8 + kc + 4) * 72 + m0 + lr    ]);
            a[3] = __float_as_uint(AsS[(g8 * 8 + kc + 4) * 72 + m0 + lr + 8]);
            #pragma unroll
            for (int j = 0; j < 13; j++) {
                unsigned b[2];
                b[0] = __float_as_uint(BsS[(g8 * 8 + kc    ) * 232 + nb0 + 8 * j + lr]);
                b[1] = __float_as_uint(BsS[(g8 * 8 + kc + 4) * 232 + nb0 + 8 * j + lr]);
                mma8(acc[j], a, b);
            }
        }
    }

    const float sbn = on_g[cch] * rsqrtf(on_v[cch] + 1e-5f);
    const float sh  = on_bb[cch] - on_m[cch] * sbn + on_b[cch] * sbn;
    const float* gres = g + ((size_t)n * Cc + cch) * Pp;
    float* zb = out + ((size_t)n * Cc + cch) * Pp;

    #pragma unroll
    for (int half = 0; half < 2; half++) {
        int q = m0 + lr + half * 8;
        #pragma unroll
        for (int j = 0; j < 13; j++) {
            int v = nb0 + 8 * j + 2 * kc;
            if (v < 204) {
                float2 rv = *(const float2*)(gres + (size_t)q * 204 + v);
                float va = acc[j][half * 2]     * sbn + sh + rv.x;
                float vb = acc[j][half * 2 + 1] * sbn + sh + rv.y;
                va = (va > 0.f) ? va : 0.1f * va;
                vb = (vb > 0.f) ? vb : 0.1f * vb;
                *(float2*)(zb + (size_t)q * 204 + v) = make_float2(rna_f(va), rna_f(vb));
            }
        }
    }
}

// ---------------- launch: two free-running segment chains; wpe on s2 ----------------
extern "C" void kernel_launch(void* const* d_in, const int* in_sizes, int n_in,
                              void* d_out, int out_size)
{
    const float* x      = (const float*)d_in[0];
    const float* A      = (const float*)d_in[1];
    const float* gcn_w  = (const float*)d_in[2];
    const float* gcn_b  = (const float*)d_in[3];
    const float* gcn_g  = (const float*)d_in[4];
    const float* gcn_bb = (const float*)d_in[5];
    const float* gcn_m  = (const float*)d_in[6];
    const float* gcn_v  = (const float*)d_in[7];
    const float* pe     = (const float*)d_in[8];
    const float* qkv_w  = (const float*)d_in[9];
    const float* qkv_b  = (const float*)d_in[10];
    const float* alphas = (const float*)d_in[11];
    const float* att1s  = (const float*)d_in[12];
    const float* on_w   = (const float*)d_in[13];
    const float* on_b   = (const float*)d_in[14];
    const float* on_g   = (const float*)d_in[15];
    const float* on_bb  = (const float*)d_in[16];
    const float* on_m   = (const float*)d_in[17];
    const float* on_v   = (const float*)d_in[18];
    const float* ff_w   = (const float*)d_in[19];
    const float* ff_b   = (const float*)d_in[20];
    const float* ff_g   = (const float*)d_in[21];
    const float* ff_bb  = (const float*)d_in[22];
    const float* ff_m   = (const float*)d_in[23];
    const float* ff_v   = (const float*)d_in[24];
    float* out = (float*)d_out;

    float *ph, *pg, *pqk, *pwpe, *patt, *pattp, *pG2, *pwt, *pA2;
    cudaGetSymbolAddress((void**)&ph,    d_h);
    cudaGetSymbolAddress((void**)&pg,    d_g);
    cudaGetSymbolAddress((void**)&pqk,   d_qk);
    cudaGetSymbolAddress((void**)&pwpe,  d_wpe);
    cudaGetSymbolAddress((void**)&patt,  d_att);
    cudaGetSymbolAddress((void**)&pattp, d_attp);
    cudaGetSymbolAddress((void**)&pG2,   d_G2);
    cudaGetSymbolAddress((void**)&pwt,   d_wt);
    cudaGetSymbolAddress((void**)&pA2,   d_A2);

    static int init_done = 0;
    static cudaStream_t s2;
    static cudaEvent_t evP, evW, evS;
    if (!init_done) {
        cudaFuncSetAttribute(conv_mma<MODE_BIAS, 0>, cudaFuncAttributeMaxDynamicSharedMemorySize, CV_SMEM);
        cudaFuncSetAttribute(conv_mma<MODE_BIAS, 1>, cudaFuncAttributeMaxDynamicSharedMemorySize, CV_SMEM);
        cudaFuncSetAttribute(conv_mma<MODE_ADD2D, 1>, cudaFuncAttributeMaxDynamicSharedMemorySize, CV_SMEM);
        cudaFuncSetAttribute(conv_mma<MODE_NONE, 1>, cudaFuncAttributeMaxDynamicSharedMemorySize, CV_SMEM);
        cudaFuncSetAttribute(conv_mma<MODE_BN_RES_LEAKY, 0>, cudaFuncAttributeMaxDynamicSharedMemorySize, CV_SMEM);
        cudaFuncSetAttribute(adj_mma, cudaFuncAttributeMaxDynamicSharedMemorySize, AD_SMEM);
        cudaFuncSetAttribute(attn_mma, cudaFuncAttributeMaxDynamicSharedMemorySize, AT_SMEM);
        cudaFuncSetAttribute(z_mma, cudaFuncAttributeMaxDynamicSharedMemorySize, ZM_SMEM);
        cudaStreamCreateWithFlags(&s2, cudaStreamNonBlocking);
        cudaEventCreateWithFlags(&evP, cudaEventDisableTiming);
        cudaEventCreateWithFlags(&evW, cudaEventDisableTiming);
        cudaEventCreateWithFlags(&evS, cudaEventDisableTiming);
        init_done = 1;
    }

    dim3 blk(256);

    // Stream 0: prep + full chain for segment A (n 0..15)
    prep_kernel<<<(4096 + 6144 + 4096 + 12288 + 208 * 208 + 255) / 256, blk>>>(
        gcn_w, qkv_w, ff_w, on_w, A, pwt, pA2);
    cudaEventRecord(evP, 0);

    conv_mma<MODE_BIAS, 1><<<dim3(Pp / 256, 1, NB), blk, CV_SMEM>>>(
        x, pwt + WT_GCN, gcn_b, nullptr, nullptr, nullptr, nullptr, nullptr, nullptr,
        ph, Cc, Cc, 0);

    adj_mma<<<dim3((NB * Cc * Tt) / 64, 1, 1), blk, AD_SMEM>>>(
        ph, pA2, x, gcn_g, gcn_bb, gcn_m, gcn_v, pg, 0);

    // Stream s2: wpe first (off the critical path), then segment B chain
    cudaStreamWaitEvent(s2, evP, 0);
    conv_mma<MODE_BIAS, 0><<<dim3(Pp / 256, 2, 1), blk, CV_SMEM, s2>>>(
        pe, pwt + WT_QKV, qkv_b, nullptr, nullptr, nullptr, nullptr, nullptr, nullptr,
        pwpe, Cc, OQKV, 0);
    cudaEventRecord(evW, s2);

    conv_mma<MODE_BIAS, 1><<<dim3(Pp / 256, 1, NB), blk, CV_SMEM, s2>>>(
        x, pwt + WT_GCN, gcn_b, nullptr, nullptr, nullptr, nullptr, nullptr, nullptr,
        ph, Cc, Cc, NB);

    adj_mma<<<dim3((NB * Cc * Tt) / 64, 1, 1), blk, AD_SMEM, s2>>>(
        ph, pA2, x, gcn_g, gcn_bb, gcn_m, gcn_v, pg, NB * Cc * Tt);

    // Stream 0 continues segment A (K3 needs wpe from s2)
    cudaStreamWaitEvent(0, evW, 0);
    conv_mma<MODE_ADD2D, 1><<<dim3(Pp / 256, 2, NB), blk, CV_SMEM>>>(
        pg, pwt + WT_QKV, nullptr, pwpe, nullptr, nullptr, nullptr, nullptr, nullptr,
        pqk, Cc, OQKV, 0);

    attn_mma<<<dim3(Hh, NB, 4), blk, AT_SMEM>>>(pqk, pattp, 0);
    attn_combine_kernel<<<(NB * Hh * Tt * Tt + 255) / 256, blk>>>(pattp, alphas, att1s, patt, 0);

    conv_mma<MODE_NONE, 1><<<dim3(Pp / 256, 3, NB), blk, CV_SMEM>>>(
        pg, pwt + WT_W2, nullptr, nullptr, nullptr, nullptr, nullptr, nullptr, nullptr,
        pG2, Cc, HC, 0);

    z_mma<<<dim3(Cc, NB), blk, ZM_SMEM>>>(
        pG2, patt, pg, on_b, on_g, on_bb, on_m, on_v, ph, 0);

    conv_mma<MODE_BN_RES_LEAKY, 0><<<dim3(Pp / 256, 1, NB), blk, CV_SMEM>>>(
        ph, pwt + WT_FF, ff_b, nullptr, pg, ff_g, ff_bb, ff_m, ff_v,
        out, Cc, Cc, 0);

    // Stream s2 continues segment B
    conv_mma<MODE_ADD2D, 1><<<dim3(Pp / 256, 2, NB), blk, CV_SMEM, s2>>>(
        pg, pwt + WT_QKV, nullptr, pwpe, nullptr, nullptr, nullptr, nullptr, nullptr,
        pqk, Cc, OQKV, NB);

    attn_mma<<<dim3(Hh, NB, 4), blk, AT_SMEM, s2>>>(pqk, pattp, NB);
    attn_combine_kernel<<<(NB * Hh * Tt * Tt + 255) / 256, blk, 0, s2>>>(
        pattp, alphas, att1s, patt, NB);

    conv_mma<MODE_NONE, 1><<<dim3(Pp / 256, 3, NB), blk, CV_SMEM, s2>>>(
        pg, pwt + WT_W2, nullptr, nullptr, nullptr, nullptr, nullptr, nullptr, nullptr,
        pG2, Cc, HC, NB);

    z_mma<<<dim3(Cc, NB), blk, ZM_SMEM, s2>>>(
        pG2, patt, pg, on_b, on_g, on_bb, on_m, on_v, ph, NB);

    conv_mma<MODE_BN_RES_LEAKY, 0><<<dim3(Pp / 256, 1, NB), blk, CV_SMEM, s2>>>(
        ph, pwt + WT_FF, ff_b, nullptr, pg, ff_g, ff_bb, ff_m, ff_v,
        out, Cc, Cc, NB);
    cudaEventRecord(evS, s2);

    cudaStreamWaitEvent(0, evS, 0);
}

// round 15
// speedup vs baseline: 1.0150x; 1.0150x over previous
#include <cuda_runtime.h>
#include <math.h>
#include <stdint.h>

#define Nn   32
#define Cc   64
#define Tt   64
#define Vv   204
#define Hh   3
#define QKd  16
#define Pp   13056
#define OQKV 96
#define HC   192
#define NB   16

__device__ float d_h   [(size_t)Nn * Cc * Pp + 64];
__device__ float d_g   [(size_t)Nn * Cc * Pp + 64];
__device__ float d_qk  [(size_t)Nn * OQKV * Pp + 64];
__device__ float d_wpe [(size_t)OQKV * Pp];
__device__ float d_att [(size_t)Nn * Hh * Tt * Tt];
__device__ float d_attp[(size_t)4 * Nn * Hh * Tt * Tt];
__device__ float d_G2  [(size_t)Nn * HC * Pp + 64];
__device__ float d_wt  [4096 + 6144 + 4096 + 12288];
__device__ float d_A2  [208 * 208];

#define WT_GCN 0
#define WT_QKV 4096
#define WT_FF  10240
#define WT_W2  14336

enum { MODE_BIAS = 0, MODE_ADD2D = 1, MODE_BN_RES_LEAKY = 2, MODE_NONE = 3 };

__device__ __forceinline__ unsigned cvt_tf32(float f) {
    unsigned u; asm("cvt.rna.tf32.f32 %0, %1;" : "=r"(u) : "f"(f)); return u;
}
__device__ __forceinline__ float rna_f(float f) { return __uint_as_float(cvt_tf32(f)); }

__device__ __forceinline__ void mma8(float* d, const unsigned* a, const unsigned* b) {
    asm volatile(
        "mma.sync.aligned.m16n8k8.row.col.f32.tf32.tf32.f32 "
        "{%0,%1,%2,%3},{%4,%5,%6,%7},{%8,%9},{%0,%1,%2,%3};"
        : "+f"(d[0]), "+f"(d[1]), "+f"(d[2]), "+f"(d[3])
        : "r"(a[0]), "r"(a[1]), "r"(a[2]), "r"(a[3]), "r"(b[0]), "r"(b[1]));
}
__device__ __forceinline__ uint32_t smem_u32(const void* p) {
    return (uint32_t)__cvta_generic_to_shared(p);
}
__device__ __forceinline__ void cpa16(uint32_t dst, const void* src) {
    asm volatile("cp.async.cg.shared.global [%0],[%1],16;" :: "r"(dst), "l"(src));
}
__device__ __forceinline__ void cpa16z(uint32_t dst, const void* src, int sz) {
    asm volatile("cp.async.cg.shared.global [%0],[%1],16,%2;" :: "r"(dst), "l"(src), "r"(sz));
}
#define CP_COMMIT() asm volatile("cp.async.commit_group;")
#define CP_WAIT0()  asm volatile("cp.async.wait_group 0;")
#define CP_WAIT2()  asm volatile("cp.async.wait_group 2;")

// ============================================================================
__global__ void prep_kernel(const float* __restrict__ gcn_w, const float* __restrict__ qkv_w,
                            const float* __restrict__ ff_w, const float* __restrict__ on_w,
                            const float* __restrict__ A,
                            float* __restrict__ wt, float* __restrict__ A2)
{
    int i = blockIdx.x * 256 + threadIdx.x;
    if (i < 4096) { wt[WT_GCN + i] = rna_f(gcn_w[i]); return; }
    i -= 4096;
    if (i < 6144) { wt[WT_QKV + i] = rna_f(qkv_w[i]); return; }
    i -= 6144;
    if (i < 4096) { wt[WT_FF + i] = rna_f(ff_w[i]); return; }
    i -= 4096;
    if (i < 12288) {
        int o = i >> 6, cc = i & 63;
        int s = o >> 6, c = o & 63;
        wt[WT_W2 + i] = rna_f(on_w[(size_t)c * HC + s * 64 + cc]);
        return;
    }
    i -= 12288;
    if (i < 208 * 208) {
        int u = i / 208, v = i % 208;
        A2[i] = (u < 204 && v < 204) ? rna_f(A[(size_t)u * 204 + v]) : 0.f;
    }
}

// ============================================================================
// conv_mma: whole-K-resident (Kc=64). One cp.async burst, ONE sync, zero
// mainloop barriers. A [64][68] + B [64][264] = 83KB/CTA, 2 CTAs/SM.
// ============================================================================
#define CV_ASZ (64 * 68)
#define CV_BSZ (64 * 264)
#define CV_SMEM ((CV_ASZ + CV_BSZ) * 4)

template <int MODE, int ROUND>
__global__ __launch_bounds__(256, 2)
void conv_mma(const float* __restrict__ in, const float* __restrict__ Wt,
              const float* __restrict__ bias, const float* __restrict__ add2d,
              const float* __restrict__ res,
              const float* __restrict__ bng, const float* __restrict__ bnb,
              const float* __restrict__ bnm, const float* __restrict__ bnv,
              float* __restrict__ out, int Oc, int nbase)
{
    extern __shared__ float sm[];
    float* As = sm;                 // [64 rows (o)][68 (k pad)]
    float* Bs = sm + CV_ASZ;        // [64 (k)][264 (p pad)]

    const int n  = blockIdx.z + nbase;
    const int pt = blockIdx.x * 256;
    const int ot = blockIdx.y * 64;
    const int tid = threadIdx.x, lane = tid & 31, warp = tid >> 5;
    const int wm = warp & 1, wn = warp >> 1;
    const int m0 = wm * 32, n0 = wn * 64;
    const int lr = lane >> 2, kc = lane & 3;

    const float* inN = in + (size_t)n * 64 * Pp + pt;

    // Load A (whole [64][64] weight tile)
    #pragma unroll
    for (int i = 0; i < 4; i++) {
        int e = tid + 256 * i;            // 0..1023
        int row = e >> 4, grp = e & 15;
        int o = ot + row;
        int ok = (o < Oc);
        cpa16z(smem_u32(&As[row * 68 + grp * 4]),
               ok ? (Wt + (size_t)o * 64 + grp * 4) : Wt, ok ? 16 : 0);
    }
    // Load B (whole [64][256] input tile)
    #pragma unroll
    for (int i = 0; i < 16; i++) {
        int e = tid + 256 * i;            // 0..4095
        int k = e >> 6, grp = e & 63;
        cpa16(smem_u32(&Bs[k * 264 + grp * 4]), inN + (size_t)k * Pp + grp * 4);
    }
    CP_COMMIT();
    CP_WAIT0();
    __syncthreads();

    float acc[2][8][4];
    #pragma unroll
    for (int f = 0; f < 2; f++)
        #pragma unroll
        for (int j = 0; j < 8; j++)
            #pragma unroll
            for (int q = 0; q < 4; q++) acc[f][j][q] = 0.f;

    #pragma unroll
    for (int kg = 0; kg < 8; kg++) {      // 8 k-groups of 8, NO barriers
        unsigned a[2][4];
        #pragma unroll
        for (int f = 0; f < 2; f++) {
            a[f][0] = __float_as_uint(As[(m0 + f * 16 + lr    ) * 68 + kg * 8 + kc    ]);
            a[f][1] = __float_as_uint(As[(m0 + f * 16 + lr + 8) * 68 + kg * 8 + kc    ]);
            a[f][2] = __float_as_uint(As[(m0 + f * 16 + lr    ) * 68 + kg * 8 + kc + 4]);
            a[f][3] = __float_as_uint(As[(m0 + f * 16 + lr + 8) * 68 + kg * 8 + kc + 4]);
        }
        #pragma unroll
        for (int j = 0; j < 8; j++) {
            unsigned b[2];
            b[0] = __float_as_uint(Bs[(kg * 8 + kc    ) * 264 + n0 + 8 * j + lr]);
            b[1] = __float_as_uint(Bs[(kg * 8 + kc + 4) * 264 + n0 + 8 * j + lr]);
            mma8(acc[0][j], a[0], b);
            mma8(acc[1][j], a[1], b);
        }
    }

    #pragma unroll
    for (int f = 0; f < 2; f++) {
        #pragma unroll
        for (int half = 0; half < 2; half++) {
            int o = ot + m0 + f * 16 + lr + half * 8;
            if (o >= Oc) continue;
            size_t obase = ((size_t)n * Oc + o) * Pp;
            if (MODE == MODE_NONE) {
                #pragma unroll
                for (int j = 0; j < 8; j++) {
                    int p = pt + n0 + 8 * j + 2 * kc;
                    float va = acc[f][j][half * 2], vb = acc[f][j][half * 2 + 1];
                    if (ROUND) { va = rna_f(va); vb = rna_f(vb); }
                    *(float2*)(out + obase + p) = make_float2(va, vb);
                }
            } else if (MODE == MODE_BIAS) {
                float b = bias[o];
                #pragma unroll
                for (int j = 0; j < 8; j++) {
                    int p = pt + n0 + 8 * j + 2 * kc;
                    float va = acc[f][j][half * 2] + b, vb = acc[f][j][half * 2 + 1] + b;
                    if (ROUND) { va = rna_f(va); vb = rna_f(vb); }
                    *(float2*)(out + obase + p) = make_float2(va, vb);
                }
            } else if (MODE == MODE_ADD2D) {
                size_t abase = (size_t)o * Pp;
                #pragma unroll
                for (int j = 0; j < 8; j++) {
                    int p = pt + n0 + 8 * j + 2 * kc;
                    float2 av = *(const float2*)(add2d + abase + p);
                    float va = acc[f][j][half * 2] + av.x, vb = acc[f][j][half * 2 + 1] + av.y;
                    if (ROUND) { va = rna_f(va); vb = rna_f(vb); }
                    *(float2*)(out + obase + p) = make_float2(va, vb);
                }
            } else {
                float s  = bng[o] * rsqrtf(bnv[o] + 1e-5f);
                float sh = bnb[o] - bnm[o] * s + bias[o] * s;
                #pragma unroll
                for (int j = 0; j < 8; j++) {
                    int p = pt + n0 + 8 * j + 2 * kc;
                    float2 rv = *(const float2*)(res + obase + p);
                    float va = acc[f][j][half * 2]     * s + sh + rv.x;
                    float vb = acc[f][j][half * 2 + 1] * s + sh + rv.y;
                    va = (va > 0.f) ? va : 0.1f * va;
                    vb = (vb > 0.f) ? vb : 0.1f * vb;
                    if (ROUND) { va = rna_f(va); vb = rna_f(vb); }
                    *(float2*)(out + obase + p) = make_float2(va, vb);
                }
            }
        }
    }
}

// ============================================================================
// adj_mma (R14 M=64 version)
// ============================================================================
#define AD_ASZ (64 * 20)
#define AD_BSZ (208 * 20)
#define AD_SMEM (4 * (AD_ASZ + AD_BSZ) * 4)

__global__ __launch_bounds__(256, 2)
void adj_mma(const float* __restrict__ h, const float* __restrict__ A2,
             const float* __restrict__ x,
             const float* __restrict__ bng, const float* __restrict__ bnb,
             const float* __restrict__ bnm, const float* __restrict__ bnv,
             float* __restrict__ out, int rbase)
{
    extern __shared__ float sm[];
    float* As = sm;
    float* Bs = sm + 4 * AD_ASZ;

    const int rt = blockIdx.x * 64 + rbase;
    const int tid = threadIdx.x, lane = tid & 31, warp = tid >> 5;
    const int wm = warp & 3, wn = warp >> 2;
    const int m0 = wm * 16, nb0 = wn * 104;
    const int lr = lane >> 2, kc = lane & 3;

    const int ch  = (rt >> 6) & 63;
    const float s  = bng[ch] * rsqrtf(bnv[ch] + 1e-5f);
    const float sh = bnb[ch] - bnm[ch] * s;

    float acc[13][4];
    #pragma unroll
    for (int j = 0; j < 13; j++)
        #pragma unroll
        for (int q = 0; q < 4; q++) acc[j][q] = 0.f;

    const int arow = tid >> 2, agrp = tid & 3;
    const int NCH = 13;

    auto prefetch = [&](int c, int stage) {
        float* BsS = Bs + stage * AD_BSZ;
        #pragma unroll
        for (int i = 0; i < 4; i++) {
            int e = tid + 256 * i;
            if (e < 832) {
                int u = e >> 2, grp = e & 3;
                cpa16(smem_u32(&BsS[u * 20 + grp * 4]), A2 + (size_t)u * 208 + c * 16 + grp * 4);
            }
        }
        float* AsS = As + stage * AD_ASZ;
        cpa16(smem_u32(&AsS[arow * 20 + agrp * 4]),
              h + (size_t)(rt + arow) * 204 + c * 16 + agrp * 4);
    };

    prefetch(0, 0); CP_COMMIT();
    prefetch(1, 1); CP_COMMIT();

    for (int c = 0; c < NCH; c++) {
        if (c + 2 < NCH) prefetch(c + 2, (c + 2) & 3);
        CP_COMMIT();
        CP_WAIT2();
        __syncthreads();

        const float* AsS = As + (c & 3) * AD_ASZ;
        const float* BsS = Bs + (c & 3) * AD_BSZ;
        #pragma unroll
        for (int g = 0; g < 2; g++) {
            unsigned a[4];
            a[0] = __float_as_uint(AsS[(m0 + lr    ) * 20 + g * 8 + kc    ]);
            a[1] = __float_as_uint(AsS[(m0 + lr + 8) * 20 + g * 8 + kc    ]);
            a[2] = __float_as_uint(AsS[(m0 + lr    ) * 20 + g * 8 + kc + 4]);
            a[3] = __float_as_uint(AsS[(m0 + lr + 8) * 20 + g * 8 + kc + 4]);
            #pragma unroll
            for (int j = 0; j < 13; j++) {
                unsigned b[2];
                b[0] = __float_as_uint(BsS[(nb0 + 8 * j + lr) * 20 + g * 8 + kc    ]);
                b[1] = __float_as_uint(BsS[(nb0 + 8 * j + lr) * 20 + g * 8 + kc + 4]);
                mma8(acc[j], a, b);
            }
        }
    }

    #pragma unroll
    for (int half = 0; half < 2; half++) {
        int r = rt + m0 + lr + half * 8;
        size_t rb = (size_t)r * 204;
        #pragma unroll
        for (int j = 0; j < 13; j++) {
            int u = nb0 + 8 * j + 2 * kc;
            if (u < 204) {
                float2 xv = *(const float2*)(x + rb + u);
                float va = acc[j][half * 2]     * s + sh + xv.x;
                float vb = acc[j][half * 2 + 1] * s + sh + xv.y;
                *(float2*)(out + rb + u) =
                    make_float2(rna_f(fmaxf(va, 0.f)), rna_f(fmaxf(vb, 0.f)));
            }
        }
    }
}

// ============================================================================
// attn_mma / combine / z_mma (R14 verbatim)
// ============================================================================
#define AT_QSZ (64 * 20)
#define AT_SMEM (4 * 2 * AT_QSZ * 4)

__global__ __launch_bounds__(256, 4)
void attn_mma(const float* __restrict__ qk, float* __restrict__ part, int nbase)
{
    extern __shared__ float sm[];
    float* Qs = sm;
    float* Ks = sm + 4 * AT_QSZ;

    const int hh = blockIdx.x, n = blockIdx.y + nbase, z = blockIdx.z;
    const int cc0 = z * 4;
    const int tid = threadIdx.x, lane = tid & 31, warp = tid >> 5;
    const int wm = warp & 3, wn = warp >> 2;
    const int m0 = wm * 16, nb0 = wn * 32;
    const int lr = lane >> 2, kc = lane & 3;

    const float* qbase = qk + ((size_t)n * OQKV + hh * QKd) * Pp;
    const float* kbase = qk + ((size_t)n * OQKV + Hh * QKd + hh * QKd) * Pp;

    const int arow = tid >> 2, agrp = tid & 3;
    const int NCH = 52;

    float acc[4][4];
    #pragma unroll
    for (int j = 0; j < 4; j++)
        #pragma unroll
        for (int q = 0; q < 4; q++) acc[j][q] = 0.f;

    auto prefetch = [&](int c, int stage) {
        int ci = cc0 + (c / 13);
        int vb = (c % 13) * 16;
        int v = vb + agrp * 4;
        int ok = (v < 204);
        const float* qs = qbase + (size_t)ci * Pp + (size_t)arow * 204 + v;
        const float* ks = kbase + (size_t)ci * Pp + (size_t)arow * 204 + v;
        cpa16z(smem_u32(&Qs[stage * AT_QSZ + arow * 20 + agrp * 4]), ok ? qs : qk, ok ? 16 : 0);
        cpa16z(smem_u32(&Ks[stage * AT_QSZ + arow * 20 + agrp * 4]), ok ? ks : qk, ok ? 16 : 0);
    };

    prefetch(0, 0); CP_COMMIT();
    prefetch(1, 1); CP_COMMIT();

    for (int c = 0; c < NCH; c++) {
        if (c + 2 < NCH) prefetch(c + 2, (c + 2) & 3);
        CP_COMMIT();
        CP_WAIT2();
        __syncthreads();

        const float* QsS = Qs + (c & 3) * AT_QSZ;
        const float* KsS = Ks + (c & 3) * AT_QSZ;
        #pragma unroll
        for (int g = 0; g < 2; g++) {
            unsigned a[4];
            a[0] = __float_as_uint(QsS[(m0 + lr    ) * 20 + g * 8 + kc    ]);
            a[1] = __float_as_uint(QsS[(m0 + lr + 8) * 20 + g * 8 + kc    ]);
            a[2] = __float_as_uint(QsS[(m0 + lr    ) * 20 + g * 8 + kc + 4]);
            a[3] = __float_as_uint(QsS[(m0 + lr + 8) * 20 + g * 8 + kc + 4]);
            #pragma unroll
            for (int j = 0; j < 4; j++) {
                unsigned b[2];
                b[0] = __float_as_uint(KsS[(nb0 + 8 * j + lr) * 20 + g * 8 + kc    ]);
                b[1] = __float_as_uint(KsS[(nb0 + 8 * j + lr) * 20 + g * 8 + kc + 4]);
                mma8(acc[j], a, b);
            }
        }
    }

    float* pb = part + (((size_t)z * Nn + n) * Hh + hh) * 4096;
    #pragma unroll
    for (int half = 0; half < 2; half++) {
        int t = m0 + lr + half * 8;
        #pragma unroll
        for (int j = 0; j < 4; j++) {
            int q = nb0 + 8 * j + 2 * kc;
            *(float2*)(pb + (size_t)t * 64 + q) =
                make_float2(acc[j][half * 2], acc[j][half * 2 + 1]);
        }
    }
}

__global__ void attn_combine_kernel(const float* __restrict__ part,
                                    const float* __restrict__ alphas,
                                    const float* __restrict__ att1s,
                                    float* __restrict__ att, int nbase)
{
    int idx = blockIdx.x * blockDim.x + threadIdx.x;
    const int seg_total = NB * Hh * Tt * Tt;
    if (idx >= seg_total) return;
    int tq = idx & (Tt * Tt - 1);
    int rest = idx >> 12;
    int h = rest % Hh;
    int n = nbase + rest / Hh;
    const int total = Nn * Hh * Tt * Tt;
    size_t gi = (((size_t)n * Hh + h) << 12) + tq;
    float p = part[gi] + part[(size_t)total + gi]
            + part[2 * (size_t)total + gi] + part[3 * (size_t)total + gi];
    const float inv = 1.0f / (float)(QKd * Vv);
    att[gi] = rna_f(tanhf(p * inv) * alphas[h] + att1s[(size_t)h * Tt * Tt + tq]);
}

#define ZM_ASZ (16 * 72)
#define ZM_BSZ (16 * 232)
#define ZM_SMEM (4 * (ZM_ASZ + ZM_BSZ) * 4)

__global__ __launch_bounds__(256, 2)
void z_mma(const float* __restrict__ G2, const float* __restrict__ att,
           const float* __restrict__ g,
           const float* __restrict__ on_b, const float* __restrict__ on_g,
           const float* __restrict__ on_bb, const float* __restrict__ on_m,
           const float* __restrict__ on_v,
           float* __restrict__ out, int nbase)
{
    extern __shared__ float sm[];
    float* As = sm;
    float* Bs = sm + 4 * ZM_ASZ;

    const int cch = blockIdx.x, n = blockIdx.y + nbase;
    const int tid = threadIdx.x, lane = tid & 31, warp = tid >> 5;
    const int wm = warp & 3, wn = warp >> 2;
    const int m0 = wm * 16, nb0 = wn * 104;
    const int lr = lane >> 2, kc = lane & 3;

    float acc[13][4];
    #pragma unroll
    for (int j = 0; j < 13; j++)
        #pragma unroll
        for (int q = 0; q < 4; q++) acc[j][q] = 0.f;

    const int NCH = 12;

    auto prefetch = [&](int c, int stage) {
        int s  = c >> 2;
        int tb = (c & 3) * 16;
        const float* gb = G2 + ((size_t)n * HC + s * 64 + cch) * Pp;
        float* BsS = Bs + stage * ZM_BSZ;
        #pragma unroll
        for (int i = 0; i < 4; i++) {
            int e = tid + 256 * i;
            if (e < 832) {
                int trow = e / 52, grp = e % 52;
                int ok = (grp < 51);
                cpa16z(smem_u32(&BsS[trow * 232 + grp * 4]),
                       ok ? (gb + (size_t)(tb + trow) * 204 + grp * 4) : gb, ok ? 16 : 0);
            }
        }
        float* AsS = As + stage * ZM_ASZ;
        int trow = tid >> 4, grp = tid & 15;
        cpa16(smem_u32(&AsS[trow * 72 + grp * 4]),
              att + ((size_t)(n * Hh + s)) * 4096 + (size_t)(tb + trow) * 64 + grp * 4);
    };

    prefetch(0, 0); CP_COMMIT();
    prefetch(1, 1); CP_COMMIT();

    for (int c = 0; c < NCH; c++) {
        if (c + 2 < NCH) prefetch(c + 2, (c + 2) & 3);
        CP_COMMIT();
        CP_WAIT2();
        __syncthreads();

        const float* AsS = As + (c & 3) * ZM_ASZ;
        const float* BsS = Bs + (c & 3) * ZM_BSZ;
        #pragma unroll
        for (int g8 = 0; g8 < 2; g8++) {
            unsigned a[4];
            a[0] = __float_as_uint(AsS[(g8 * 8 + kc    ) * 72 + m0 + lr    ]);
            a[1] = __float_as_uint(AsS[(g8 * 8 + kc    ) * 72 + m0 + lr + 8]);
            a[2] = __float_as_uint(AsS[(g8 * 8 + kc + 4) * 72 + m0 + lr    ]);
            a[3] = __float_as_uint(AsS[(g8 * 8 + kc + 4) * 72 + m0 + lr + 8]);
            #pragma unroll
            for (int j = 0; j < 13; j++) {
                unsigned b[2];
                b[0] = __float_as_uint(BsS[(g8 * 8 + kc    ) * 232 + nb0 + 8 * j + lr]);
                b[1] = __float_as_uint(BsS[(g8 * 8 + kc + 4) * 232 + nb0 + 8 * j + lr]);
                mma8(acc[j], a, b);
            }
        }
    }

    const float sbn = on_g[cch] * rsqrtf(on_v[cch] + 1e-5f);
    const float sh  = on_bb[cch] - on_m[cch] * sbn + on_b[cch] * sbn;
    const float* gres = g + ((size_t)n * Cc + cch) * Pp;
    float* zb = out + ((size_t)n * Cc + cch) * Pp;

    #pragma unroll
    for (int half = 0; half < 2; half++) {
        int q = m0 + lr + half * 8;
        #pragma unroll
        for (int j = 0; j < 13; j++) {
            int v = nb0 + 8 * j + 2 * kc;
            if (v < 204) {
                float2 rv = *(const float2*)(gres + (size_t)q * 204 + v);
                float va = acc[j][half * 2]     * sbn + sh + rv.x;
                float vb = acc[j][half * 2 + 1] * sbn + sh + rv.y;
                va = (va > 0.f) ? va : 0.1f * va;
                vb = (vb > 0.f) ? vb : 0.1f * vb;
                *(float2*)(zb + (size_t)q * 204 + v) = make_float2(rna_f(va), rna_f(vb));
            }
        }
    }
}

// ---------------- launch: two free-running segment chains; wpe on s2 ----------------
extern "C" void kernel_launch(void* const* d_in, const int* in_sizes, int n_in,
                              void* d_out, int out_size)
{
    const float* x      = (const float*)d_in[0];
    const float* A      = (const float*)d_in[1];
    const float* gcn_w  = (const float*)d_in[2];
    const float* gcn_b  = (const float*)d_in[3];
    const float* gcn_g  = (const float*)d_in[4];
    const float* gcn_bb = (const float*)d_in[5];
    const float* gcn_m  = (const float*)d_in[6];
    const float* gcn_v  = (const float*)d_in[7];
    const float* pe     = (const float*)d_in[8];
    const float* qkv_w  = (const float*)d_in[9];
    const float* qkv_b  = (const float*)d_in[10];
    const float* alphas = (const float*)d_in[11];
    const float* att1s  = (const float*)d_in[12];
    const float* on_w   = (const float*)d_in[13];
    const float* on_b   = (const float*)d_in[14];
    const float* on_g   = (const float*)d_in[15];
    const float* on_bb  = (const float*)d_in[16];
    const float* on_m   = (const float*)d_in[17];
    const float* on_v   = (const float*)d_in[18];
    const float* ff_w   = (const float*)d_in[19];
    const float* ff_b   = (const float*)d_in[20];
    const float* ff_g   = (const float*)d_in[21];
    const float* ff_bb  = (const float*)d_in[22];
    const float* ff_m   = (const float*)d_in[23];
    const float* ff_v   = (const float*)d_in[24];
    float* out = (float*)d_out;

    float *ph, *pg, *pqk, *pwpe, *patt, *pattp, *pG2, *pwt, *pA2;
    cudaGetSymbolAddress((void**)&ph,    d_h);
    cudaGetSymbolAddress((void**)&pg,    d_g);
    cudaGetSymbolAddress((void**)&pqk,   d_qk);
    cudaGetSymbolAddress((void**)&pwpe,  d_wpe);
    cudaGetSymbolAddress((void**)&patt,  d_att);
    cudaGetSymbolAddress((void**)&pattp, d_attp);
    cudaGetSymbolAddress((void**)&pG2,   d_G2);
    cudaGetSymbolAddress((void**)&pwt,   d_wt);
    cudaGetSymbolAddress((void**)&pA2,   d_A2);

    static int init_done = 0;
    static cudaStream_t s2;
    static cudaEvent_t evP, evW, evS;
    if (!init_done) {
        cudaFuncSetAttribute(conv_mma<MODE_BIAS, 0>, cudaFuncAttributeMaxDynamicSharedMemorySize, CV_SMEM);
        cudaFuncSetAttribute(conv_mma<MODE_BIAS, 1>, cudaFuncAttributeMaxDynamicSharedMemorySize, CV_SMEM);
        cudaFuncSetAttribute(conv_mma<MODE_ADD2D, 1>, cudaFuncAttributeMaxDynamicSharedMemorySize, CV_SMEM);
        cudaFuncSetAttribute(conv_mma<MODE_NONE, 1>, cudaFuncAttributeMaxDynamicSharedMemorySize, CV_SMEM);
        cudaFuncSetAttribute(conv_mma<MODE_BN_RES_LEAKY, 0>, cudaFuncAttributeMaxDynamicSharedMemorySize, CV_SMEM);
        cudaFuncSetAttribute(adj_mma, cudaFuncAttributeMaxDynamicSharedMemorySize, AD_SMEM);
        cudaFuncSetAttribute(attn_mma, cudaFuncAttributeMaxDynamicSharedMemorySize, AT_SMEM);
        cudaFuncSetAttribute(z_mma, cudaFuncAttributeMaxDynamicSharedMemorySize, ZM_SMEM);
        cudaStreamCreateWithFlags(&s2, cudaStreamNonBlocking);
        cudaEventCreateWithFlags(&evP, cudaEventDisableTiming);
        cudaEventCreateWithFlags(&evW, cudaEventDisableTiming);
        cudaEventCreateWithFlags(&evS, cudaEventDisableTiming);
        init_done = 1;
    }

    dim3 blk(256);

    // Stream 0: prep + full chain for segment A (n 0..15)
    prep_kernel<<<(4096 + 6144 + 4096 + 12288 + 208 * 208 + 255) / 256, blk>>>(
        gcn_w, qkv_w, ff_w, on_w, A, pwt, pA2);
    cudaEventRecord(evP, 0);

    conv_mma<MODE_BIAS, 1><<<dim3(Pp / 256, 1, NB), blk, CV_SMEM>>>(
        x, pwt + WT_GCN, gcn_b, nullptr, nullptr, nullptr, nullptr, nullptr, nullptr,
        ph, Cc, 0);

    adj_mma<<<dim3((NB * Cc * Tt) / 64, 1, 1), blk, AD_SMEM>>>(
        ph, pA2, x, gcn_g, gcn_bb, gcn_m, gcn_v, pg, 0);

    // Stream s2: wpe first (off the critical path), then segment B chain
    cudaStreamWaitEvent(s2, evP, 0);
    conv_mma<MODE_BIAS, 0><<<dim3(Pp / 256, 2, 1), blk, CV_SMEM, s2>>>(
        pe, pwt + WT_QKV, qkv_b, nullptr, nullptr, nullptr, nullptr, nullptr, nullptr,
        pwpe, OQKV, 0);
    cudaEventRecord(evW, s2);

    conv_mma<MODE_BIAS, 1><<<dim3(Pp / 256, 1, NB), blk, CV_SMEM, s2>>>(
        x, pwt + WT_GCN, gcn_b, nullptr, nullptr, nullptr, nullptr, nullptr, nullptr,
        ph, Cc, NB);

    adj_mma<<<dim3((NB * Cc * Tt) / 64, 1, 1), blk, AD_SMEM, s2>>>(
        ph, pA2, x, gcn_g, gcn_bb, gcn_m, gcn_v, pg, NB * Cc * Tt);

    // Stream 0 continues segment A (K3 needs wpe from s2)
    cudaStreamWaitEvent(0, evW, 0);
    conv_mma<MODE_ADD2D, 1><<<dim3(Pp / 256, 2, NB), blk, CV_SMEM>>>(
        pg, pwt + WT_QKV, nullptr, pwpe, nullptr, nullptr, nullptr, nullptr, nullptr,
        pqk, OQKV, 0);

    attn_mma<<<dim3(Hh, NB, 4), blk, AT_SMEM>>>(pqk, pattp, 0);
    attn_combine_kernel<<<(NB * Hh * Tt * Tt + 255) / 256, blk>>>(pattp, alphas, att1s, patt, 0);

    conv_mma<MODE_NONE, 1><<<dim3(Pp / 256, 3, NB), blk, CV_SMEM>>>(
        pg, pwt + WT_W2, nullptr, nullptr, nullptr, nullptr, nullptr, nullptr, nullptr,
        pG2, HC, 0);

    z_mma<<<dim3(Cc, NB), blk, ZM_SMEM>>>(
        pG2, patt, pg, on_b, on_g, on_bb, on_m, on_v, ph, 0);

    conv_mma<MODE_BN_RES_LEAKY, 0><<<dim3(Pp / 256, 1, NB), blk, CV_SMEM>>>(
        ph, pwt + WT_FF, ff_b, nullptr, pg, ff_g, ff_bb, ff_m, ff_v,
        out, Cc, 0);

    // Stream s2 continues segment B
    conv_mma<MODE_ADD2D, 1><<<dim3(Pp / 256, 2, NB), blk, CV_SMEM, s2>>>(
        pg, pwt + WT_QKV, nullptr, pwpe, nullptr, nullptr, nullptr, nullptr, nullptr,
        pqk, OQKV, NB);

    attn_mma<<<dim3(Hh, NB, 4), blk, AT_SMEM, s2>>>(pqk, pattp, NB);
    attn_combine_kernel<<<(NB * Hh * Tt * Tt + 255) / 256, blk, 0, s2>>>(
        pattp, alphas, att1s, patt, NB);

    conv_mma<MODE_NONE, 1><<<dim3(Pp / 256, 3, NB), blk, CV_SMEM, s2>>>(
        pg, pwt + WT_W2, nullptr, nullptr, nullptr, nullptr, nullptr, nullptr, nullptr,
        pG2, HC, NB);

    z_mma<<<dim3(Cc, NB), blk, ZM_SMEM, s2>>>(
        pG2, patt, pg, on_b, on_g, on_bb, on_m, on_v, ph, NB);

    conv_mma<MODE_BN_RES_LEAKY, 0><<<dim3(Pp / 256, 1, NB), blk, CV_SMEM, s2>>>(
        ph, pwt + WT_FF, ff_b, nullptr, pg, ff_g, ff_bb, ff_m, ff_v,
        out, Cc, NB);
    cudaEventRecord(evS, s2);

    cudaStreamWaitEvent(0, evS, 0);
}

// round 16
// speedup vs baseline: 1.0222x; 1.0071x over previous
#include <cuda_runtime.h>
#include <math.h>
#include <stdint.h>

#define Nn   32
#define Cc   64
#define Tt   64
#define Vv   204
#define Hh   3
#define QKd  16
#define Pp   13056
#define OQKV 96
#define HC   192
#define NB   16

__device__ float d_h   [(size_t)Nn * Cc * Pp + 64];
__device__ float d_g   [(size_t)Nn * Cc * Pp + 64];
__device__ float d_qk  [(size_t)Nn * OQKV * Pp + 64];
__device__ float d_wpe [(size_t)OQKV * Pp];
__device__ float d_att [(size_t)Nn * Hh * Tt * Tt];
__device__ float d_attp[(size_t)4 * Nn * Hh * Tt * Tt];
__device__ float d_G2  [(size_t)Nn * HC * Pp + 64];
__device__ float d_wt  [26624];     // gcn(4096) | qkv+w2 packed(18432) | ff(4096)
__device__ float d_A2  [208 * 208];

#define WT_GCN 0
#define WT_QKG 4096
#define WT_FF  22528

enum { MODE_BIAS = 0, MODE_ADD2D = 1, MODE_BN_RES_LEAKY = 2, MODE_NONE = 3, MODE_FUSED = 4 };

__device__ __forceinline__ unsigned cvt_tf32(float f) {
    unsigned u; asm("cvt.rna.tf32.f32 %0, %1;" : "=r"(u) : "f"(f)); return u;
}
__device__ __forceinline__ float rna_f(float f) { return __uint_as_float(cvt_tf32(f)); }

__device__ __forceinline__ void mma8(float* d, const unsigned* a, const unsigned* b) {
    asm volatile(
        "mma.sync.aligned.m16n8k8.row.col.f32.tf32.tf32.f32 "
        "{%0,%1,%2,%3},{%4,%5,%6,%7},{%8,%9},{%0,%1,%2,%3};"
        : "+f"(d[0]), "+f"(d[1]), "+f"(d[2]), "+f"(d[3])
        : "r"(a[0]), "r"(a[1]), "r"(a[2]), "r"(a[3]), "r"(b[0]), "r"(b[1]));
}
__device__ __forceinline__ uint32_t smem_u32(const void* p) {
    return (uint32_t)__cvta_generic_to_shared(p);
}
__device__ __forceinline__ void cpa16(uint32_t dst, const void* src) {
    asm volatile("cp.async.cg.shared.global [%0],[%1],16;" :: "r"(dst), "l"(src));
}
__device__ __forceinline__ void cpa16z(uint32_t dst, const void* src, int sz) {
    asm volatile("cp.async.cg.shared.global [%0],[%1],16,%2;" :: "r"(dst), "l"(src), "r"(sz));
}
#define CP_COMMIT() asm volatile("cp.async.commit_group;")
#define CP_WAIT0()  asm volatile("cp.async.wait_group 0;")
#define CP_WAIT2()  asm volatile("cp.async.wait_group 2;")

// ============================================================================
__global__ void prep_kernel(const float* __restrict__ gcn_w, const float* __restrict__ qkv_w,
                            const float* __restrict__ ff_w, const float* __restrict__ on_w,
                            const float* __restrict__ A,
                            float* __restrict__ wt, float* __restrict__ A2)
{
    int i = blockIdx.x * 256 + threadIdx.x;
    if (i < 4096) { wt[WT_GCN + i] = rna_f(gcn_w[i]); return; }
    i -= 4096;
    if (i < 6144) { wt[WT_QKG + i] = rna_f(qkv_w[i]); return; }   // rows 0..95
    i -= 6144;
    if (i < 12288) {                                              // rows 96..287 = W2
        int o = i >> 6, cc = i & 63;
        int s = o >> 6, c = o & 63;
        wt[WT_QKG + 6144 + i] = rna_f(on_w[(size_t)c * HC + s * 64 + cc]);
        return;
    }
    i -= 12288;
    if (i < 4096) { wt[WT_FF + i] = rna_f(ff_w[i]); return; }
    i -= 4096;
    if (i < 208 * 208) {
        int u = i / 208, v = i % 208;
        A2[i] = (u < 204 && v < 204) ? rna_f(A[(size_t)u * 204 + v]) : 0.f;
    }
}

// ============================================================================
// conv_mma: whole-K-resident (Kc=64), one sync, zero mainloop barriers.
// MODE_FUSED: o<96 -> qk (+wpe via add2d), o>=96 -> G2 (via res ptr), rounded.
// ============================================================================
#define CV_ASZ (64 * 68)
#define CV_BSZ (64 * 264)
#define CV_SMEM ((CV_ASZ + CV_BSZ) * 4)

template <int MODE, int ROUND>
__global__ __launch_bounds__(256, 2)
void conv_mma(const float* __restrict__ in, const float* __restrict__ Wt,
              const float* __restrict__ bias, const float* __restrict__ add2d,
              float* __restrict__ res,
              const float* __restrict__ bng, const float* __restrict__ bnb,
              const float* __restrict__ bnm, const float* __restrict__ bnv,
              float* __restrict__ out, int Oc, int nbase)
{
    extern __shared__ float sm[];
    float* As = sm;
    float* Bs = sm + CV_ASZ;

    const int n  = blockIdx.z + nbase;
    const int pt = blockIdx.x * 256;
    const int ot = blockIdx.y * 64;
    const int tid = threadIdx.x, lane = tid & 31, warp = tid >> 5;
    const int wm = warp & 1, wn = warp >> 1;
    const int m0 = wm * 32, n0 = wn * 64;
    const int lr = lane >> 2, kc = lane & 3;

    const float* inN = in + (size_t)n * 64 * Pp + pt;

    #pragma unroll
    for (int i = 0; i < 4; i++) {
        int e = tid + 256 * i;
        int row = e >> 4, grp = e & 15;
        int o = ot + row;
        int ok = (o < Oc);
        cpa16z(smem_u32(&As[row * 68 + grp * 4]),
               ok ? (Wt + (size_t)o * 64 + grp * 4) : Wt, ok ? 16 : 0);
    }
    #pragma unroll
    for (int i = 0; i < 16; i++) {
        int e = tid + 256 * i;
        int k = e >> 6, grp = e & 63;
        cpa16(smem_u32(&Bs[k * 264 + grp * 4]), inN + (size_t)k * Pp + grp * 4);
    }
    CP_COMMIT();
    CP_WAIT0();
    __syncthreads();

    float acc[2][8][4];
    #pragma unroll
    for (int f = 0; f < 2; f++)
        #pragma unroll
        for (int j = 0; j < 8; j++)
            #pragma unroll
            for (int q = 0; q < 4; q++) acc[f][j][q] = 0.f;

    #pragma unroll
    for (int kg = 0; kg < 8; kg++) {
        unsigned a[2][4];
        #pragma unroll
        for (int f = 0; f < 2; f++) {
            a[f][0] = __float_as_uint(As[(m0 + f * 16 + lr    ) * 68 + kg * 8 + kc    ]);
            a[f][1] = __float_as_uint(As[(m0 + f * 16 + lr + 8) * 68 + kg * 8 + kc    ]);
            a[f][2] = __float_as_uint(As[(m0 + f * 16 + lr    ) * 68 + kg * 8 + kc + 4]);
            a[f][3] = __float_as_uint(As[(m0 + f * 16 + lr + 8) * 68 + kg * 8 + kc + 4]);
        }
        #pragma unroll
        for (int j = 0; j < 8; j++) {
            unsigned b[2];
            b[0] = __float_as_uint(Bs[(kg * 8 + kc    ) * 264 + n0 + 8 * j + lr]);
            b[1] = __float_as_uint(Bs[(kg * 8 + kc + 4) * 264 + n0 + 8 * j + lr]);
            mma8(acc[0][j], a[0], b);
            mma8(acc[1][j], a[1], b);
        }
    }

    #pragma unroll
    for (int f = 0; f < 2; f++) {
        #pragma unroll
        for (int half = 0; half < 2; half++) {
            int o = ot + m0 + f * 16 + lr + half * 8;
            if (o >= Oc) continue;
            if (MODE == MODE_FUSED) {
                if (o < OQKV) {
                    size_t obase = ((size_t)n * OQKV + o) * Pp;
                    size_t abase = (size_t)o * Pp;
                    #pragma unroll
                    for (int j = 0; j < 8; j++) {
                        int p = pt + n0 + 8 * j + 2 * kc;
                        float2 av = *(const float2*)(add2d + abase + p);
                        *(float2*)(out + obase + p) =
                            make_float2(rna_f(acc[f][j][half * 2] + av.x),
                                        rna_f(acc[f][j][half * 2 + 1] + av.y));
                    }
                } else {
                    size_t obase = ((size_t)n * HC + (o - OQKV)) * Pp;
                    #pragma unroll
                    for (int j = 0; j < 8; j++) {
                        int p = pt + n0 + 8 * j + 2 * kc;
                        *(float2*)(res + obase + p) =
                            make_float2(rna_f(acc[f][j][half * 2]),
                                        rna_f(acc[f][j][half * 2 + 1]));
                    }
                }
            } else {
                size_t obase = ((size_t)n * Oc + o) * Pp;
                if (MODE == MODE_BIAS) {
                    float b = bias[o];
                    #pragma unroll
                    for (int j = 0; j < 8; j++) {
                        int p = pt + n0 + 8 * j + 2 * kc;
                        float va = acc[f][j][half * 2] + b, vb = acc[f][j][half * 2 + 1] + b;
                        if (ROUND) { va = rna_f(va); vb = rna_f(vb); }
                        *(float2*)(out + obase + p) = make_float2(va, vb);
                    }
                } else if (MODE == MODE_BN_RES_LEAKY) {
                    float s  = bng[o] * rsqrtf(bnv[o] + 1e-5f);
                    float sh = bnb[o] - bnm[o] * s + bias[o] * s;
                    #pragma unroll
                    for (int j = 0; j < 8; j++) {
                        int p = pt + n0 + 8 * j + 2 * kc;
                        float2 rv = *(const float2*)(res + obase + p);
                        float va = acc[f][j][half * 2]     * s + sh + rv.x;
                        float vb = acc[f][j][half * 2 + 1] * s + sh + rv.y;
                        va = (va > 0.f) ? va : 0.1f * va;
                        vb = (vb > 0.f) ? vb : 0.1f * vb;
                        if (ROUND) { va = rna_f(va); vb = rna_f(vb); }
                        *(float2*)(out + obase + p) = make_float2(va, vb);
                    }
                }
            }
        }
    }
}

// ============================================================================
// adj_mma (R15 verbatim)
// ============================================================================
#define AD_ASZ (64 * 20)
#define AD_BSZ (208 * 20)
#define AD_SMEM (4 * (AD_ASZ + AD_BSZ) * 4)

__global__ __launch_bounds__(256, 2)
void adj_mma(const float* __restrict__ h, const float* __restrict__ A2,
             const float* __restrict__ x,
             const float* __restrict__ bng, const float* __restrict__ bnb,
             const float* __restrict__ bnm, const float* __restrict__ bnv,
             float* __restrict__ out, int rbase)
{
    extern __shared__ float sm[];
    float* As = sm;
    float* Bs = sm + 4 * AD_ASZ;

    const int rt = blockIdx.x * 64 + rbase;
    const int tid = threadIdx.x, lane = tid & 31, warp = tid >> 5;
    const int wm = warp & 3, wn = warp >> 2;
    const int m0 = wm * 16, nb0 = wn * 104;
    const int lr = lane >> 2, kc = lane & 3;

    const int ch  = (rt >> 6) & 63;
    const float s  = bng[ch] * rsqrtf(bnv[ch] + 1e-5f);
    const float sh = bnb[ch] - bnm[ch] * s;

    float acc[13][4];
    #pragma unroll
    for (int j = 0; j < 13; j++)
        #pragma unroll
        for (int q = 0; q < 4; q++) acc[j][q] = 0.f;

    const int arow = tid >> 2, agrp = tid & 3;
    const int NCH = 13;

    auto prefetch = [&](int c, int stage) {
        float* BsS = Bs + stage * AD_BSZ;
        #pragma unroll
        for (int i = 0; i < 4; i++) {
            int e = tid + 256 * i;
            if (e < 832) {
                int u = e >> 2, grp = e & 3;
                cpa16(smem_u32(&BsS[u * 20 + grp * 4]), A2 + (size_t)u * 208 + c * 16 + grp * 4);
            }
        }
        float* AsS = As + stage * AD_ASZ;
        cpa16(smem_u32(&AsS[arow * 20 + agrp * 4]),
              h + (size_t)(rt + arow) * 204 + c * 16 + agrp * 4);
    };

    prefetch(0, 0); CP_COMMIT();
    prefetch(1, 1); CP_COMMIT();

    for (int c = 0; c < NCH; c++) {
        if (c + 2 < NCH) prefetch(c + 2, (c + 2) & 3);
        CP_COMMIT();
        CP_WAIT2();
        __syncthreads();

        const float* AsS = As + (c & 3) * AD_ASZ;
        const float* BsS = Bs + (c & 3) * AD_BSZ;
        #pragma unroll
        for (int g = 0; g < 2; g++) {
            unsigned a[4];
            a[0] = __float_as_uint(AsS[(m0 + lr    ) * 20 + g * 8 + kc    ]);
            a[1] = __float_as_uint(AsS[(m0 + lr + 8) * 20 + g * 8 + kc    ]);
            a[2] = __float_as_uint(AsS[(m0 + lr    ) * 20 + g * 8 + kc + 4]);
            a[3] = __float_as_uint(AsS[(m0 + lr + 8) * 20 + g * 8 + kc + 4]);
            #pragma unroll
            for (int j = 0; j < 13; j++) {
                unsigned b[2];
                b[0] = __float_as_uint(BsS[(nb0 + 8 * j + lr) * 20 + g * 8 + kc    ]);
                b[1] = __float_as_uint(BsS[(nb0 + 8 * j + lr) * 20 + g * 8 + kc + 4]);
                mma8(acc[j], a, b);
            }
        }
    }

    #pragma unroll
    for (int half = 0; half < 2; half++) {
        int r = rt + m0 + lr + half * 8;
        size_t rb = (size_t)r * 204;
        #pragma unroll
        for (int j = 0; j < 13; j++) {
            int u = nb0 + 8 * j + 2 * kc;
            if (u < 204) {
                float2 xv = *(const float2*)(x + rb + u);
                float va = acc[j][half * 2]     * s + sh + xv.x;
                float vb = acc[j][half * 2 + 1] * s + sh + xv.y;
                *(float2*)(out + rb + u) =
                    make_float2(rna_f(fmaxf(va, 0.f)), rna_f(fmaxf(vb, 0.f)));
            }
        }
    }
}

// ============================================================================
// attn_mma / combine / z_mma (R15 verbatim)
// ============================================================================
#define AT_QSZ (64 * 20)
#define AT_SMEM (4 * 2 * AT_QSZ * 4)

__global__ __launch_bounds__(256, 4)
void attn_mma(const float* __restrict__ qk, float* __restrict__ part, int nbase)
{
    extern __shared__ float sm[];
    float* Qs = sm;
    float* Ks = sm + 4 * AT_QSZ;

    const int hh = blockIdx.x, n = blockIdx.y + nbase, z = blockIdx.z;
    const int cc0 = z * 4;
    const int tid = threadIdx.x, lane = tid & 31, warp = tid >> 5;
    const int wm = warp & 3, wn = warp >> 2;
    const int m0 = wm * 16, nb0 = wn * 32;
    const int lr = lane >> 2, kc = lane & 3;

    const float* qbase = qk + ((size_t)n * OQKV + hh * QKd) * Pp;
    const float* kbase = qk + ((size_t)n * OQKV + Hh * QKd + hh * QKd) * Pp;

    const int arow = tid >> 2, agrp = tid & 3;
    const int NCH = 52;

    float acc[4][4];
    #pragma unroll
    for (int j = 0; j < 4; j++)
        #pragma unroll
        for (int q = 0; q < 4; q++) acc[j][q] = 0.f;

    auto prefetch = [&](int c, int stage) {
        int ci = cc0 + (c / 13);
        int vb = (c % 13) * 16;
        int v = vb + agrp * 4;
        int ok = (v < 204);
        const float* qs = qbase + (size_t)ci * Pp + (size_t)arow * 204 + v;
        const float* ks = kbase + (size_t)ci * Pp + (size_t)arow * 204 + v;
        cpa16z(smem_u32(&Qs[stage * AT_QSZ + arow * 20 + agrp * 4]), ok ? qs : qk, ok ? 16 : 0);
        cpa16z(smem_u32(&Ks[stage * AT_QSZ + arow * 20 + agrp * 4]), ok ? ks : qk, ok ? 16 : 0);
    };

    prefetch(0, 0); CP_COMMIT();
    prefetch(1, 1); CP_COMMIT();

    for (int c = 0; c < NCH; c++) {
        if (c + 2 < NCH) prefetch(c + 2, (c + 2) & 3);
        CP_COMMIT();
        CP_WAIT2();
        __syncthreads();

        const float* QsS = Qs + (c & 3) * AT_QSZ;
        const float* KsS = Ks + (c & 3) * AT_QSZ;
        #pragma unroll
        for (int g = 0; g < 2; g++) {
            unsigned a[4];
            a[0] = __float_as_uint(QsS[(m0 + lr    ) * 20 + g * 8 + kc    ]);
            a[1] = __float_as_uint(QsS[(m0 + lr + 8) * 20 + g * 8 + kc    ]);
            a[2] = __float_as_uint(QsS[(m0 + lr    ) * 20 + g * 8 + kc + 4]);
            a[3] = __float_as_uint(QsS[(m0 + lr + 8) * 20 + g * 8 + kc + 4]);
            #pragma unroll
            for (int j = 0; j < 4; j++) {
                unsigned b[2];
                b[0] = __float_as_uint(KsS[(nb0 + 8 * j + lr) * 20 + g * 8 + kc    ]);
                b[1] = __float_as_uint(KsS[(nb0 + 8 * j + lr) * 20 + g * 8 + kc + 4]);
                mma8(acc[j], a, b);
            }
        }
    }

    float* pb = part + (((size_t)z * Nn + n) * Hh + hh) * 4096;
    #pragma unroll
    for (int half = 0; half < 2; half++) {
        int t = m0 + lr + half * 8;
        #pragma unroll
        for (int j = 0; j < 4; j++) {
            int q = nb0 + 8 * j + 2 * kc;
            *(float2*)(pb + (size_t)t * 64 + q) =
                make_float2(acc[j][half * 2], acc[j][half * 2 + 1]);
        }
    }
}

__global__ void attn_combine_kernel(const float* __restrict__ part,
                                    const float* __restrict__ alphas,
                                    const float* __restrict__ att1s,
                                    float* __restrict__ att, int nbase)
{
    int idx = blockIdx.x * blockDim.x + threadIdx.x;
    const int seg_total = NB * Hh * Tt * Tt;
    if (idx >= seg_total) return;
    int tq = idx & (Tt * Tt - 1);
    int rest = idx >> 12;
    int h = rest % Hh;
    int n = nbase + rest / Hh;
    const int total = Nn * Hh * Tt * Tt;
    size_t gi = (((size_t)n * Hh + h) << 12) + tq;
    float p = part[gi] + part[(size_t)total + gi]
            + part[2 * (size_t)total + gi] + part[3 * (size_t)total + gi];
    const float inv = 1.0f / (float)(QKd * Vv);
    att[gi] = rna_f(tanhf(p * inv) * alphas[h] + att1s[(size_t)h * Tt * Tt + tq]);
}

#define ZM_ASZ (16 * 72)
#define ZM_BSZ (16 * 232)
#define ZM_SMEM (4 * (ZM_ASZ + ZM_BSZ) * 4)

__global__ __launch_bounds__(256, 2)
void z_mma(const float* __restrict__ G2, const float* __restrict__ att,
           const float* __restrict__ g,
           const float* __restrict__ on_b, const float* __restrict__ on_g,
           const float* __restrict__ on_bb, const float* __restrict__ on_m,
           const float* __restrict__ on_v,
           float* __restrict__ out, int nbase)
{
    extern __shared__ float sm[];
    float* As = sm;
    float* Bs = sm + 4 * ZM_ASZ;

    const int cch = blockIdx.x, n = blockIdx.y + nbase;
    const int tid = threadIdx.x, lane = tid & 31, warp = tid >> 5;
    const int wm = warp & 3, wn = warp >> 2;
    const int m0 = wm * 16, nb0 = wn * 104;
    const int lr = lane >> 2, kc = lane & 3;

    float acc[13][4];
    #pragma unroll
    for (int j = 0; j < 13; j++)
        #pragma unroll
        for (int q = 0; q < 4; q++) acc[j][q] = 0.f;

    const int NCH = 12;

    auto prefetch = [&](int c, int stage) {
        int s  = c >> 2;
        int tb = (c & 3) * 16;
        const float* gb = G2 + ((size_t)n * HC + s * 64 + cch) * Pp;
        float* BsS = Bs + stage * ZM_BSZ;
        #pragma unroll
        for (int i = 0; i < 4; i++) {
            int e = tid + 256 * i;
            if (e < 832) {
                int trow = e / 52, grp = e % 52;
                int ok = (grp < 51);
                cpa16z(smem_u32(&BsS[trow * 232 + grp * 4]),
                       ok ? (gb + (size_t)(tb + trow) * 204 + grp * 4) : gb, ok ? 16 : 0);
            }
        }
        float* AsS = As + stage * ZM_ASZ;
        int trow = tid >> 4, grp = tid & 15;
        cpa16(smem_u32(&AsS[trow * 72 + grp * 4]),
              att + ((size_t)(n * Hh + s)) * 4096 + (size_t)(tb + trow) * 64 + grp * 4);
    };

    prefetch(0, 0); CP_COMMIT();
    prefetch(1, 1); CP_COMMIT();

    for (int c = 0; c < NCH; c++) {
        if (c + 2 < NCH) prefetch(c + 2, (c + 2) & 3);
        CP_COMMIT();
        CP_WAIT2();
        __syncthreads();

        const float* AsS = As + (c & 3) * ZM_ASZ;
        const float* BsS = Bs + (c & 3) * ZM_BSZ;
        #pragma unroll
        for (int g8 = 0; g8 < 2; g8++) {
            unsigned a[4];
            a[0] = __float_as_uint(AsS[(g8 * 8 + kc    ) * 72 + m0 + lr    ]);
            a[1] = __float_as_uint(AsS[(g8 * 8 + kc    ) * 72 + m0 + lr + 8]);
            a[2] = __float_as_uint(AsS[(g8 * 8 + kc + 4) * 72 + m0 + lr    ]);
            a[3] = __float_as_uint(AsS[(g8 * 8 + kc + 4) * 72 + m0 + lr + 8]);
            #pragma unroll
            for (int j = 0; j < 13; j++) {
                unsigned b[2];
                b[0] = __float_as_uint(BsS[(g8 * 8 + kc    ) * 232 + nb0 + 8 * j + lr]);
                b[1] = __float_as_uint(BsS[(g8 * 8 + kc + 4) * 232 + nb0 + 8 * j + lr]);
                mma8(acc[j], a, b);
            }
        }
    }

    const float sbn = on_g[cch] * rsqrtf(on_v[cch] + 1e-5f);
    const float sh  = on_bb[cch] - on_m[cch] * sbn + on_b[cch] * sbn;
    const float* gres = g + ((size_t)n * Cc + cch) * Pp;
    float* zb = out + ((size_t)n * Cc + cch) * Pp;

    #pragma unroll
    for (int half = 0; half < 2; half++) {
        int q = m0 + lr + half * 8;
        #pragma unroll
        for (int j = 0; j < 13; j++) {
            int v = nb0 + 8 * j + 2 * kc;
            if (v < 204) {
                float2 rv = *(const float2*)(gres + (size_t)q * 204 + v);
                float va = acc[j][half * 2]     * sbn + sh + rv.x;
                float vb = acc[j][half * 2 + 1] * sbn + sh + rv.y;
                va = (va > 0.f) ? va : 0.1f * va;
                vb = (vb > 0.f) ? vb : 0.1f * vb;
                *(float2*)(zb + (size_t)q * 204 + v) = make_float2(rna_f(va), rna_f(vb));
            }
        }
    }
}

// ---------------- launch: two free-running chains, fused qk+G2 stage ----------------
extern "C" void kernel_launch(void* const* d_in, const int* in_sizes, int n_in,
                              void* d_out, int out_size)
{
    const float* x      = (const float*)d_in[0];
    const float* A      = (const float*)d_in[1];
    const float* gcn_w  = (const float*)d_in[2];
    const float* gcn_b  = (const float*)d_in[3];
    const float* gcn_g  = (const float*)d_in[4];
    const float* gcn_bb = (const float*)d_in[5];
    const float* gcn_m  = (const float*)d_in[6];
    const float* gcn_v  = (const float*)d_in[7];
    const float* pe     = (const float*)d_in[8];
    const float* qkv_w  = (const float*)d_in[9];
    const float* qkv_b  = (const float*)d_in[10];
    const float* alphas = (const float*)d_in[11];
    const float* att1s  = (const float*)d_in[12];
    const float* on_w   = (const float*)d_in[13];
    const float* on_b   = (const float*)d_in[14];
    const float* on_g   = (const float*)d_in[15];
    const float* on_bb  = (const float*)d_in[16];
    const float* on_m   = (const float*)d_in[17];
    const float* on_v   = (const float*)d_in[18];
    const float* ff_w   = (const float*)d_in[19];
    const float* ff_b   = (const float*)d_in[20];
    const float* ff_g   = (const float*)d_in[21];
    const float* ff_bb  = (const float*)d_in[22];
    const float* ff_m   = (const float*)d_in[23];
    const float* ff_v   = (const float*)d_in[24];
    float* out = (float*)d_out;

    float *ph, *pg, *pqk, *pwpe, *patt, *pattp, *pG2, *pwt, *pA2;
    cudaGetSymbolAddress((void**)&ph,    d_h);
    cudaGetSymbolAddress((void**)&pg,    d_g);
    cudaGetSymbolAddress((void**)&pqk,   d_qk);
    cudaGetSymbolAddress((void**)&pwpe,  d_wpe);
    cudaGetSymbolAddress((void**)&patt,  d_att);
    cudaGetSymbolAddress((void**)&pattp, d_attp);
    cudaGetSymbolAddress((void**)&pG2,   d_G2);
    cudaGetSymbolAddress((void**)&pwt,   d_wt);
    cudaGetSymbolAddress((void**)&pA2,   d_A2);

    static int init_done = 0;
    static cudaStream_t s2;
    static cudaEvent_t evP, evW, evS;
    if (!init_done) {
        cudaFuncSetAttribute(conv_mma<MODE_BIAS, 0>, cudaFuncAttributeMaxDynamicSharedMemorySize, CV_SMEM);
        cudaFuncSetAttribute(conv_mma<MODE_BIAS, 1>, cudaFuncAttributeMaxDynamicSharedMemorySize, CV_SMEM);
        cudaFuncSetAttribute(conv_mma<MODE_FUSED, 1>, cudaFuncAttributeMaxDynamicSharedMemorySize, CV_SMEM);
        cudaFuncSetAttribute(conv_mma<MODE_BN_RES_LEAKY, 0>, cudaFuncAttributeMaxDynamicSharedMemorySize, CV_SMEM);
        cudaFuncSetAttribute(adj_mma, cudaFuncAttributeMaxDynamicSharedMemorySize, AD_SMEM);
        cudaFuncSetAttribute(attn_mma, cudaFuncAttributeMaxDynamicSharedMemorySize, AT_SMEM);
        cudaFuncSetAttribute(z_mma, cudaFuncAttributeMaxDynamicSharedMemorySize, ZM_SMEM);
        cudaStreamCreateWithFlags(&s2, cudaStreamNonBlocking);
        cudaEventCreateWithFlags(&evP, cudaEventDisableTiming);
        cudaEventCreateWithFlags(&evW, cudaEventDisableTiming);
        cudaEventCreateWithFlags(&evS, cudaEventDisableTiming);
        init_done = 1;
    }

    dim3 blk(256);

    // Stream 0: prep + segment A chain
    prep_kernel<<<(4096 + 6144 + 12288 + 4096 + 208 * 208 + 255) / 256, blk>>>(
        gcn_w, qkv_w, ff_w, on_w, A, pwt, pA2);
    cudaEventRecord(evP, 0);

    conv_mma<MODE_BIAS, 1><<<dim3(Pp / 256, 1, NB), blk, CV_SMEM>>>(
        x, pwt + WT_GCN, gcn_b, nullptr, nullptr, nullptr, nullptr, nullptr, nullptr,
        ph, Cc, 0);

    adj_mma<<<dim3((NB * Cc * Tt) / 64, 1, 1), blk, AD_SMEM>>>(
        ph, pA2, x, gcn_g, gcn_bb, gcn_m, gcn_v, pg, 0);

    // Stream s2: wpe first, then segment B chain
    cudaStreamWaitEvent(s2, evP, 0);
    conv_mma<MODE_BIAS, 0><<<dim3(Pp / 256, 2, 1), blk, CV_SMEM, s2>>>(
        pe, pwt + WT_QKG, qkv_b, nullptr, nullptr, nullptr, nullptr, nullptr, nullptr,
        pwpe, OQKV, 0);
    cudaEventRecord(evW, s2);

    conv_mma<MODE_BIAS, 1><<<dim3(Pp / 256, 1, NB), blk, CV_SMEM, s2>>>(
        x, pwt + WT_GCN, gcn_b, nullptr, nullptr, nullptr, nullptr, nullptr, nullptr,
        ph, Cc, NB);

    adj_mma<<<dim3((NB * Cc * Tt) / 64, 1, 1), blk, AD_SMEM, s2>>>(
        ph, pA2, x, gcn_g, gcn_bb, gcn_m, gcn_v, pg, NB * Cc * Tt);

    // Stream 0: fused qk+G2 (needs wpe), attn, z, ff
    cudaStreamWaitEvent(0, evW, 0);
    conv_mma<MODE_FUSED, 1><<<dim3(Pp / 256, 5, NB), blk, CV_SMEM>>>(
        pg, pwt + WT_QKG, nullptr, pwpe, pG2, nullptr, nullptr, nullptr, nullptr,
        pqk, OQKV + HC, 0);

    attn_mma<<<dim3(Hh, NB, 4), blk, AT_SMEM>>>(pqk, pattp, 0);
    attn_combine_kernel<<<(NB * Hh * Tt * Tt + 255) / 256, blk>>>(pattp, alphas, att1s, patt, 0);

    z_mma<<<dim3(Cc, NB), blk, ZM_SMEM>>>(
        pG2, patt, pg, on_b, on_g, on_bb, on_m, on_v, ph, 0);

    conv_mma<MODE_BN_RES_LEAKY, 0><<<dim3(Pp / 256, 1, NB), blk, CV_SMEM>>>(
        ph, pwt + WT_FF, ff_b, nullptr, pg, ff_g, ff_bb, ff_m, ff_v,
        out, Cc, 0);

    // Stream s2: fused qk+G2, attn, z, ff for segment B
    conv_mma<MODE_FUSED, 1><<<dim3(Pp / 256, 5, NB), blk, CV_SMEM, s2>>>(
        pg, pwt + WT_QKG, nullptr, pwpe, pG2, nullptr, nullptr, nullptr, nullptr,
        pqk, OQKV + HC, NB);

    attn_mma<<<dim3(Hh, NB, 4), blk, AT_SMEM, s2>>>(pqk, pattp, NB);
    attn_combine_kernel<<<(NB * Hh * Tt * Tt + 255) / 256, blk, 0, s2>>>(
        pattp, alphas, att1s, patt, NB);

    z_mma<<<dim3(Cc, NB), blk, ZM_SMEM, s2>>>(
        pG2, patt, pg, on_b, on_g, on_bb, on_m, on_v, ph, NB);

    conv_mma<MODE_BN_RES_LEAKY, 0><<<dim3(Pp / 256, 1, NB), blk, CV_SMEM, s2>>>(
        ph, pwt + WT_FF, ff_b, nullptr, pg, ff_g, ff_bb, ff_m, ff_v,
        out, Cc, NB);
    cudaEventRecord(evS, s2);

    cudaStreamWaitEvent(0, evS, 0);
}